// round 1
// baseline (speedup 1.0000x reference)
#include <cuda_runtime.h>

#define BB 512
#define SS 200
#define EMB 256
#define NSK 300

// Folded projection vectors: out[e] = mask * (qf*A[e] + att*N[e] + mast*M[e] + C[e])
__device__ __align__(16) float g_A[EMB];
__device__ __align__(16) float g_N[EMB];
__device__ __align__(16) float g_M[EMB];
__device__ __align__(16) float g_C[EMB];

__global__ void te_precompute(const float* __restrict__ skill_w,
                              const float* __restrict__ skill_b,
                              const float* __restrict__ att_w,
                              const float* __restrict__ att_b,
                              const float* __restrict__ mast_w,
                              const float* __restrict__ mast_b,
                              const float* __restrict__ proj_w,
                              const float* __restrict__ proj_b) {
    int e = threadIdx.x;  // 0..255
    const float* row = proj_w + e * 64;  // proj_w is [EMB, 64] row-major
    float a = 0.f, n = 0.f, m = 0.f, c = proj_b[e];
#pragma unroll
    for (int i = 0; i < 21; i++) {
        float w = row[i];
        a = fmaf(skill_w[i], w, a);
        c = fmaf(skill_b[i], w, c);
    }
#pragma unroll
    for (int i = 0; i < 21; i++) {
        float w = row[21 + i];
        n = fmaf(att_w[i], w, n);
        c = fmaf(att_b[i], w, c);
    }
#pragma unroll
    for (int i = 0; i < 22; i++) {
        float w = row[42 + i];
        m = fmaf(mast_w[i], w, m);
        c = fmaf(mast_b[i], w, c);
    }
    g_A[e] = a; g_N[e] = n; g_M[e] = m; g_C[e] = c;
}

__global__ __launch_bounds__(256) void te_main(const int* __restrict__ q,
                                               const int* __restrict__ r,
                                               float* __restrict__ out) {
    __shared__ int   s_idx[SS];    // clipped skill index
    __shared__ int   s_inc[SS];    // packed: valid ? (1 | (r<<16)) : 0
    __shared__ float s_qf[SS];     // raw q as float
    __shared__ float s_mask[SS];   // valid ? 1 : 0
    __shared__ float s_att[SS];
    __shared__ float s_mast[SS];

    const int b   = blockIdx.x;
    const int tid = threadIdx.x;

    // ---- load row into shared ----
    for (int t = tid; t < SS; t += 256) {
        int qi = q[b * SS + t];
        int ri = r[b * SS + t];
        bool valid = (qi >= 0) && (qi < NSK);
        int ci = qi < 0 ? 0 : (qi >= NSK ? NSK - 1 : qi);
        s_idx[t]  = ci;
        s_inc[t]  = valid ? (1 | (ri << 16)) : 0;
        s_qf[t]   = (float)qi;
        s_mask[t] = valid ? 1.0f : 0.0f;
    }
    __syncthreads();

    // ---- parallel triangular running-count: O(S^2) comparisons, no serial chain ----
    // attempts[t] = #{t' <= t : idx[t']==idx[t] && valid[t']}
    // correct[t]  = sum of r over those t'
    if (tid < SS) {
        const int myq = s_idx[tid];
        int acc = 0;  // low 16 bits = attempts, high 16 = correct (both <= 200)
#pragma unroll 4
        for (int t2 = 0; t2 <= tid; t2++) {
            if (s_idx[t2] == myq) acc += s_inc[t2];
        }
        float att = (float)(acc & 0xFFFF);
        float cor = (float)(acc >> 16);
        s_att[tid]  = att;
        s_mast[tid] = cor / fmaxf(att, 1.0f);
    }
    __syncthreads();

    // ---- epilogue: 4 time-steps x 64 threads, float4 stores ----
    const int te = tid & 63;   // which float4 of the 256-wide embedding
    const int tz = tid >> 6;   // which of 4 interleaved time steps

    const float4 A = ((const float4*)g_A)[te];
    const float4 N = ((const float4*)g_N)[te];
    const float4 M = ((const float4*)g_M)[te];
    const float4 C = ((const float4*)g_C)[te];

    float4* obase = (float4*)out + (size_t)b * SS * 64 + te;

    for (int t = tz; t < SS; t += 4) {
        float mk = s_mask[t];
        float qf = s_qf[t];
        float at = s_att[t];
        float ms = s_mast[t];
        float4 o;
        o.x = mk * fmaf(qf, A.x, fmaf(at, N.x, fmaf(ms, M.x, C.x)));
        o.y = mk * fmaf(qf, A.y, fmaf(at, N.y, fmaf(ms, M.y, C.y)));
        o.z = mk * fmaf(qf, A.z, fmaf(at, N.z, fmaf(ms, M.z, C.z)));
        o.w = mk * fmaf(qf, A.w, fmaf(at, N.w, fmaf(ms, M.w, C.w)));
        obase[(size_t)t * 64] = o;
    }
}

extern "C" void kernel_launch(void* const* d_in, const int* in_sizes, int n_in,
                              void* d_out, int out_size) {
    const int*   q       = (const int*)d_in[0];
    const int*   r       = (const int*)d_in[1];
    // d_in[2] = qry (unused by reference output)
    const float* skill_w = (const float*)d_in[3];
    const float* skill_b = (const float*)d_in[4];
    const float* att_w   = (const float*)d_in[5];
    const float* att_b   = (const float*)d_in[6];
    const float* mast_w  = (const float*)d_in[7];
    const float* mast_b  = (const float*)d_in[8];
    const float* proj_w  = (const float*)d_in[9];
    const float* proj_b  = (const float*)d_in[10];
    float* out = (float*)d_out;

    te_precompute<<<1, 256>>>(skill_w, skill_b, att_w, att_b,
                              mast_w, mast_b, proj_w, proj_b);
    te_main<<<BB, 256>>>(q, r, out);
}